// round 15
// baseline (speedup 1.0000x reference)
#include <cuda_runtime.h>

// Problem constants (fixed by the dataset)
#define Bc   2
#define Sc   4096
#define Hc   12
#define Gc   64
#define Wc   513
#define WGc  577      // G + W
#define HALF 256      // W/2
#define BSc  (Bc * Sc)

#define N_SPLIT         16           // s-splits per 128-wide i-tile
#define N_TILES         (Bc * 32)    // 128-wide i-tiles
#define N_LOCAL_BLOCKS  (N_TILES * N_SPLIT)   // 1024
#define N_GCHUNK        96           // row-chunks per batch for global sums
#define N_GLOBAL_BLOCKS (Bc * N_GCHUNK)       // 192
// main grid = 1216 = 8 * 152 -> fully resident in one wave on GB300

#define N_IDX_MAX 128                // index arrays are B*G = 128 entries

// Scratch. Zero-initialized at module load (.bss); final_kernel re-zeroes it
// after consuming, so every kernel_launch call (and every graph replay) sees
// zeros. Plain __device__ globals -> allocation-free.
__device__ float g_probs_sum[BSc];          // accumulated local sums
__device__ float g_gs[Bc][Bc * Gc];         // global sums, one copy per consumer

// ---------------------------------------------------------------------------
// Fused main pass (proven 44.6us mainloop, unchanged except the PDL trigger):
// reads all 227 MB of probs exactly once. DRAM-bound.
// ---------------------------------------------------------------------------
__global__ __launch_bounds__(256) void main_kernel(
    const float* __restrict__ probs, const float* __restrict__ mask)
{
    if (blockIdx.x < N_LOCAL_BLOCKS) {
        const int tile  = blockIdx.x >> 4;    // 0..63
        const int split = blockIdx.x & 15;    // 0..15
        const int w     = threadIdx.x >> 5;   // 0..7
        const int lane  = threadIdx.x & 31;
        const int iw    = w & 3;              // i-subtile within block
        const int sg    = w >> 2;             // s-subgroup (0,1)

        const int b  = tile >> 5;             // 32 tiles per batch
        const int i0 = (tile & 31) << 7;      // i base (128-wide tile)
        const int i  = i0 + iw * 32 + lane;   // this thread's output token

        // s-window for this tile: [i0-256, i0+384), 640 values = 16*2*20
        const int s_start = i0 - HALF + split * 40 + sg * 20;

        const float* __restrict__ mrow = mask + b * Sc;
        float acc = 0.0f;

        #pragma unroll 1
        for (int t = 0; t < 20; ++t) {
            const int s = s_start + t;
            if (s < 0 || s >= Sc) continue;
            const int c = Gc + HALF + i - s;           // column for this i
            if (c < Gc || c >= WGc) continue;          // diagonal band edges
            const float flag = (mrow[s] >= 0.0f) ? 1.0f : 0.0f;
            const float* __restrict__ row =
                probs + (size_t)(b * Sc + s) * Hc * WGc + c;
            float a = 0.0f;
            #pragma unroll
            for (int h = 0; h < Hc; ++h)               // 12 independent loads
                a += row[(size_t)h * WGc];
            acc += flag * a;
        }

        __shared__ float red[2][4][33];
        red[sg][iw][lane] = acc;
        __syncthreads();
        if (sg == 0)                                    // warps 0..3 emit
            atomicAdd(&g_probs_sum[b * Sc + i],
                      red[0][iw][lane] + red[1][iw][lane]);
    } else {
        const int idx   = blockIdx.x - N_LOCAL_BLOCKS;  // 0..191
        const int b     = idx / N_GCHUNK;
        const int chunk = idx % N_GCHUNK;
        const int c     = threadIdx.x & 63;
        const int rg    = threadIdx.x >> 6;

        const float* __restrict__ mrow = mask + b * Sc;
        const float* __restrict__ base = probs + (size_t)b * Sc * Hc * WGc;

        float acc = 0.0f;
        const int r0 = chunk * 512;      // rows are (s*H + h), 49152 per batch
        #pragma unroll 8
        for (int r = r0 + rg; r < r0 + 512; r += 4) {
            const int s = r / Hc;
            const float flag = (mrow[s] >= 0.0f) ? 1.0f : 0.0f;
            acc += flag * base[(size_t)r * WGc + c];
        }

        __shared__ float gred[4][64];
        gred[rg][c] = acc;
        __syncthreads();
        if (rg == 0) {
            const float tot = gred[0][c] + gred[1][c] + gred[2][c] + gred[3][c];
            atomicAdd(&g_gs[0][b * Gc + c], tot);   // copy for final block 0
            atomicAdd(&g_gs[1][b * Gc + c], tot);   // copy for final block 1
        }
    }

    // PDL: signal completion so the dependent final_kernel can launch and
    // run its independent prologue while remaining blocks drain.
    cudaTriggerProgrammaticLaunchCompletion();
}

// ---------------------------------------------------------------------------
// Final: scatter + per-batch max + threshold + scratch re-zero.
// One block per batch, 1024 threads. PDL-overlapped: everything independent
// of main's output (index staging, dtype detect) runs BEFORE
// cudaGridDependencySynchronize(); only ps/gs consumption waits for main.
// ---------------------------------------------------------------------------
__global__ __launch_bounds__(1024) void final_kernel(
    const float* __restrict__ thr_p,
    const void* __restrict__ lbv, const void* __restrict__ liv,
    const void* __restrict__ gbv, const void* __restrict__ giv,
    int n, float* __restrict__ out)
{
    __shared__ float     ps[Sc];             // probs_sum for this batch (16 KB)
    __shared__ float     gs[Bc * Gc];        // global sums, BOTH batches
    __shared__ long long sidx[4][N_IDX_MAX]; // staged index words (4 KB)
    __shared__ float     smax[32];
    __shared__ int       is32;

    const int b   = blockIdx.x;
    const int tid = threadIdx.x;
    const int lane = tid & 31, wrp = tid >> 5;
    const void* const parr[4] = { lbv, liv, gbv, giv };

    // ---- independent prologue (overlaps main's tail under PDL) ----
    // raw 8-byte words, first n/2 of each array: covers the ENTIRE buffer if
    // dtype is int32 (n*4 bytes), the lower half if int64. Safe either way.
    int detect = 0;
    if (tid < 4 * (n / 2)) {
        const int a = tid / (n / 2), k = tid % (n / 2);
        const long long v = ((const long long*)parr[a])[k];
        sidx[a][k] = v;
        // dtype detect on glob_i words: int32 data viewed as int64 yields
        // values outside [0, 2^31).
        if (a == 3 && (v < 0 || v >= (1LL << 31))) detect = 1;
    }
    if (tid == 0) is32 = 0;
    const float thr_raw = thr_p[0];          // also independent of main
    __syncthreads();
    if (detect) atomicOr(&is32, 1);
    __syncthreads();
    if (!is32 && tid < 4 * (n / 2)) {        // int64: upper-half words
        const int a = tid / (n / 2), k = n / 2 + tid % (n / 2);
        sidx[a][k] = ((const long long*)parr[a])[k];
    }

    // ---- wait for main_kernel's results to be visible ----
    cudaGridDependencySynchronize();

    ((float4*)ps)[tid] = ((const float4*)(g_probs_sum + b * Sc))[tid];
    if (tid < Bc * Gc) gs[tid] = g_gs[b][tid];
    __syncthreads();

    // scratch re-zero for the next replay (off the critical path)
    ((float4*)(g_probs_sum + b * Sc))[tid] = make_float4(0.f, 0.f, 0.f, 0.f);
    if (tid < Bc * Gc) g_gs[b][tid] = 0.0f;

    // ---- scatter: probs_sum[lb, li] += global_sum[gb, gi] (smem-only) ----
    if (tid < n) {
        int lb, li, gb, gi;
        if (is32) {
            lb = ((const int*)sidx[0])[tid];
            li = ((const int*)sidx[1])[tid];
            gb = ((const int*)sidx[2])[tid];
            gi = ((const int*)sidx[3])[tid];
        } else {
            lb = (int)sidx[0][tid];
            li = (int)sidx[1][tid];
            gb = (int)sidx[2][tid];
            gi = (int)sidx[3][tid];
        }
        if (lb == b) atomicAdd(&ps[li], gs[gb * Gc + gi]);
    }
    __syncthreads();

    // ---- per-batch max (4 values/thread, shuffle + smem reduce) ----
    const float4 v = ((const float4*)ps)[tid];
    float m = fmaxf(fmaxf(v.x, v.y), fmaxf(v.z, v.w));
    #pragma unroll
    for (int off = 16; off >= 1; off >>= 1)
        m = fmaxf(m, __shfl_xor_sync(0xffffffffu, m, off));
    if (lane == 0) smax[wrp] = m;
    __syncthreads();
    if (wrp == 0) {
        float mm = smax[lane];
        #pragma unroll
        for (int off = 16; off >= 1; off >>= 1)
            mm = fmaxf(mm, __shfl_xor_sync(0xffffffffu, mm, off));
        if (lane == 0) smax[0] = mm;
    }
    __syncthreads();
    const float pm  = smax[0];
    const float thr = fmaxf(1e-5f, thr_raw);

    // ---- outputs: [ new_attention_mask (B*S) | scores (B*S) ] ----
    const float4 sc = make_float4(v.x / pm, v.y / pm, v.z / pm, v.w / pm);
    float4 mk;
    mk.x = (sc.x < thr) ? -10000.0f : 0.0f;
    mk.y = (sc.y < thr) ? -10000.0f : 0.0f;
    mk.z = (sc.z < thr) ? -10000.0f : 0.0f;
    mk.w = (sc.w < thr) ? -10000.0f : 0.0f;
    ((float4*)(out + b * Sc))[tid]       = mk;
    ((float4*)(out + BSc + b * Sc))[tid] = sc;
}

// ---------------------------------------------------------------------------
// launch — 2 graph nodes; final_kernel uses programmatic dependent launch so
// its prologue overlaps main_kernel's tail. Allocation-free.
// Inputs (metadata order): attention_mask f32, attention_probs f32,
// keep_threshold f32[1], max_num_global_attn_indices (unused),
// loc_b, loc_i, glob_b, glob_i.
// ---------------------------------------------------------------------------
extern "C" void kernel_launch(void* const* d_in, const int* in_sizes, int n_in,
                              void* d_out, int out_size)
{
    const float* mask  = (const float*)d_in[0];
    const float* probs = (const float*)d_in[1];
    const float* thr   = (const float*)d_in[2];
    const void*  lb    = d_in[4];
    const void*  li    = d_in[5];
    const void*  gb    = d_in[6];
    const void*  gi    = d_in[7];
    float* out = (float*)d_out;
    const int n_idx = in_sizes[4];

    main_kernel<<<N_LOCAL_BLOCKS + N_GLOBAL_BLOCKS, 256>>>(probs, mask);

    cudaLaunchConfig_t cfg = {};
    cfg.gridDim  = dim3(Bc, 1, 1);
    cfg.blockDim = dim3(1024, 1, 1);
    cfg.stream   = 0;                 // same (captured) default stream
    cudaLaunchAttribute attrs[1];
    attrs[0].id = cudaLaunchAttributeProgrammaticStreamSerialization;
    attrs[0].val.programmaticStreamSerializationAllowed = 1;
    cfg.attrs    = attrs;
    cfg.numAttrs = 1;
    cudaLaunchKernelEx(&cfg, final_kernel, thr, lb, li, gb, gi, n_idx, out);
}